// round 14
// baseline (speedup 1.0000x reference)
#include <cuda_runtime.h>
#include <cuda_bf16.h>
#include <cstdint>

#define NROWS 16384
#define DIM   512
#define KNN   10
#define NC2   12          // candidates kept per scanner thread
#define NCAND 24          // candidates per row

// ---- device scratch (allocation-free rule) ----
__device__ float          g_xw[NROWS * DIM];   // x @ A
__device__ __nv_bfloat16  g_bf[NROWS * DIM];   // x bf16, k-permuted per 16-group
__device__ float          g_sq[NROWS];         // fp32 row norms (recall scan)
__device__ float2         g_sqd[NROWS];        // df64 row norms (exact rescore)
__device__ int            g_cand[NROWS * NCAND];
__device__ int            g_idx[NROWS * KNN];

// ---- helpers ----
__device__ __forceinline__ float2 df_add(float2 a, float2 b) {
    float s = a.x + b.x;
    float e = (fabsf(a.x) >= fabsf(b.x)) ? ((a.x - s) + b.x) : ((b.x - s) + a.x);
    e += a.y + b.y;
    float hi = s + e;
    return make_float2(hi, e - (hi - s));
}
__device__ __forceinline__ uint32_t smem_u32(const void* p) {
    uint32_t a;
    asm("{ .reg .u64 t; cvta.to.shared.u64 t, %1; cvt.u32.u64 %0, t; }" : "=r"(a) : "l"(p));
    return a;
}
__device__ __forceinline__ void cpa16(uint32_t s, const void* g) {
    asm volatile("cp.async.cg.shared.global [%0], [%1], 16;" :: "r"(s), "l"(g));
}

// m16n8k16 bf16
#define MMA_BF16(c, a, b) \
    asm volatile("mma.sync.aligned.m16n8k16.row.col.f32.bf16.bf16.f32 " \
        "{%0,%1,%2,%3},{%4,%5,%6,%7},{%8,%9},{%0,%1,%2,%3};" \
        : "+f"((c)[0]), "+f"((c)[1]), "+f"((c)[2]), "+f"((c)[3]) \
        : "r"((a)[0]), "r"((a)[1]), "r"((a)[2]), "r"((a)[3]), \
          "r"((b)[0]), "r"((b)[1]))

// ================= prep: round to bf16 + permute k within each 16-group =================
// Pair order per 16-group: (0,1),(8,9),(2,3),(10,11),(4,5),(12,13),(6,7),(14,15)
// so uint32 pos 2t,2t+1 hold k-pairs (2t,2t+1),(2t+8,2t+9) -> one v2 load per fragment.
__global__ void tf_kernel(const float* __restrict__ x) {
    int gi = blockIdx.x * blockDim.x + threadIdx.x;    // 16-float group index
    const float4* src = reinterpret_cast<const float4*>(x) + (size_t)gi * 4;
    float k[16];
    float4 v0 = src[0], v1 = src[1], v2 = src[2], v3 = src[3];
    k[0]=v0.x; k[1]=v0.y; k[2]=v0.z; k[3]=v0.w;
    k[4]=v1.x; k[5]=v1.y; k[6]=v1.z; k[7]=v1.w;
    k[8]=v2.x; k[9]=v2.y; k[10]=v2.z; k[11]=v2.w;
    k[12]=v3.x; k[13]=v3.y; k[14]=v3.z; k[15]=v3.w;
    const int pi[8] = {0, 8, 2, 10, 4, 12, 6, 14};
    uint32_t o[8];
#pragma unroll
    for (int i = 0; i < 8; ++i) {
        asm("cvt.rn.bf16x2.f32 %0, %1, %2;" : "=r"(o[i]) : "f"(k[pi[i] + 1]), "f"(k[pi[i]]));
    }
    uint4* dst = reinterpret_cast<uint4*>(g_bf) + (size_t)gi * 2;
    dst[0] = make_uint4(o[0], o[1], o[2], o[3]);
    dst[1] = make_uint4(o[4], o[5], o[6], o[7]);
}

// ================= row norms (fp32 + df64) =================
__global__ void sq_kernel(const float* __restrict__ x) {
    int row  = (blockIdx.x * blockDim.x + threadIdx.x) >> 5;
    int lane = threadIdx.x & 31;
    if (row >= NROWS) return;
    const float* xr = x + (size_t)row * DIM;
    float hi = 0.f, lo = 0.f;
#pragma unroll
    for (int k = 0; k < 16; ++k) {
        float a = xr[lane + 32 * k];
        float p = a * a;
        float e = fmaf(a, a, -p);
        float t = hi + p;
        float er = (fabsf(hi) >= fabsf(p)) ? ((hi - t) + p) : ((p - t) + hi);
        lo += er + e;
        hi = t;
    }
#pragma unroll
    for (int o = 16; o > 0; o >>= 1) {
        float oh = __shfl_xor_sync(0xffffffffu, hi, o);
        float ol = __shfl_xor_sync(0xffffffffu, lo, o);
        float s = hi + oh;
        float e = (fabsf(hi) >= fabsf(oh)) ? ((hi - s) + oh) : ((oh - s) + hi);
        e += lo + ol;
        hi = s + e;
        lo = e - (hi - s);
    }
    if (lane == 0) { g_sqd[row] = make_float2(hi, lo); g_sq[row] = hi + lo; }
}

// ================= xW = x @ A (fp32 FFMA) =================
__global__ __launch_bounds__(256, 1) void xw_kernel(const float* __restrict__ x,
                                                    const float* __restrict__ A) {
    __shared__ float As[8][132];
    __shared__ float Bs[8][132];
    const int bm = blockIdx.y * 128;
    const int bn = blockIdx.x * 128;
    const int tid = threadIdx.x;
    const int tx = tid & 15, ty = tid >> 4;
    const int lrow = tid >> 1, lcol = (tid & 1) * 4;
    const int brow = tid >> 5, bcol = (tid & 31) * 4;
    float c[8][8] = {};
    for (int k0 = 0; k0 < DIM; k0 += 8) {
        float4 av = *reinterpret_cast<const float4*>(x + (size_t)(bm + lrow) * DIM + k0 + lcol);
        float4 bv = *reinterpret_cast<const float4*>(A + (size_t)(k0 + brow) * DIM + bn + bcol);
        __syncthreads();
        As[lcol + 0][lrow] = av.x; As[lcol + 1][lrow] = av.y;
        As[lcol + 2][lrow] = av.z; As[lcol + 3][lrow] = av.w;
        *reinterpret_cast<float4*>(&Bs[brow][bcol]) = bv;
        __syncthreads();
#pragma unroll
        for (int kk = 0; kk < 8; ++kk) {
            float a[8], b[8];
            *reinterpret_cast<float4*>(a)     = *reinterpret_cast<const float4*>(&As[kk][ty * 8]);
            *reinterpret_cast<float4*>(a + 4) = *reinterpret_cast<const float4*>(&As[kk][ty * 8 + 4]);
            *reinterpret_cast<float4*>(b)     = *reinterpret_cast<const float4*>(&Bs[kk][tx * 8]);
            *reinterpret_cast<float4*>(b + 4) = *reinterpret_cast<const float4*>(&Bs[kk][tx * 8 + 4]);
#pragma unroll
            for (int m = 0; m < 8; ++m)
#pragma unroll
                for (int n = 0; n < 8; ++n) c[m][n] = fmaf(a[m], b[n], c[m][n]);
        }
    }
#pragma unroll
    for (int m = 0; m < 8; ++m) {
        float* dst = g_xw + (size_t)(bm + ty * 8 + m) * DIM + bn + tx * 8;
        *reinterpret_cast<float4*>(dst)     = make_float4(c[m][0], c[m][1], c[m][2], c[m][3]);
        *reinterpret_cast<float4*>(dst + 4) = make_float4(c[m][4], c[m][5], c[m][6], c[m][7]);
    }
}

// ================= Gram recall: bf16, 16 warps (2Mx8N, 64x32 tiles), SMEM top-k lists =================
// SMEM bytes: A stages 2x20480 @0; B stages 2x40960 @40960; sqs @122880;
//             Ds 128x132 f32 @123904; listd 256x13 f32 @191488; listi @204800. Total 218112.
__global__ __launch_bounds__(512, 1) void knn_kernel() {
    extern __shared__ char smc[];
    const uint32_t sbase = smem_u32(smc);
    float* sqs   = reinterpret_cast<float*>(smc + 122880);
    float* Ds    = reinterpret_cast<float*>(smc + 123904);
    float* listd = reinterpret_cast<float*>(smc + 191488);
    int*   listi = reinterpret_cast<int*>(smc + 204800);

    const int tid  = threadIdx.x;
    const int lane = tid & 31, wid = tid >> 5;
    const int wn = wid & 7, wm = wid >> 3;       // warp grid 2(M) x 8(N); tile 64x32
    const int g = lane >> 2, t = lane & 3;
    const int bm = blockIdx.x * 128;

    const int srow = tid >> 1, sh = tid & 1;     // scanners: tid<256, 2 per row
    const int rowg = bm + srow;

    const float FINF = __int_as_float(0x7f800000);
    if (tid < 256) {
#pragma unroll
        for (int q = 0; q < NC2; ++q) { listd[tid * 13 + q] = FINF; listi[tid * 13 + q] = 0; }
    }
    float thresh = FINF;                          // register cache of listd[NC2-1]

    for (int jt = 0; jt < 64; ++jt) {
        const int jb = jt * 256;
        __syncthreads();                 // prev j-tile scan done (sqs/Ds reuse)
        if (tid < 256) sqs[tid] = g_sq[jb + tid];

        float c[16][4];
#pragma unroll
        for (int i = 0; i < 16; ++i) { c[i][0] = 0.f; c[i][1] = 0.f; c[i][2] = 0.f; c[i][3] = 0.f; }

        // stage slab 0 (k 0..63) into buffer 0
        {
            const uint32_t sA = sbase, sB = sbase + 40960;
#pragma unroll
            for (int i = tid; i < 1024; i += 512) {          // A: 128 rows x 8 x 16B
                int r = i >> 3, cc = i & 7;
                cpa16(sA + r * 160 + cc * 16, g_bf + (size_t)(bm + r) * DIM + cc * 8);
            }
#pragma unroll
            for (int i = tid; i < 2048; i += 512) {          // B: 256 rows x 8 x 16B
                int r = i >> 3, cc = i & 7;
                cpa16(sB + r * 160 + cc * 16, g_bf + (size_t)(jb + r) * DIM + cc * 8);
            }
            asm volatile("cp.async.commit_group;" ::: "memory");
        }

        for (int slab = 0; slab < 8; ++slab) {               // 8 slabs of k=64
            const int cur = slab & 1;
            if (slab < 7) {                                  // stage next, THEN wait
                const int nxt = (slab + 1) & 1;
                const int kb = (slab + 1) * 64;
                const uint32_t sA = sbase + nxt * 20480;
                const uint32_t sB = sbase + 40960 + nxt * 40960;
#pragma unroll
                for (int i = tid; i < 1024; i += 512) {
                    int r = i >> 3, cc = i & 7;
                    cpa16(sA + r * 160 + cc * 16, g_bf + (size_t)(bm + r) * DIM + kb + cc * 8);
                }
#pragma unroll
                for (int i = tid; i < 2048; i += 512) {
                    int r = i >> 3, cc = i & 7;
                    cpa16(sB + r * 160 + cc * 16, g_bf + (size_t)(jb + r) * DIM + kb + cc * 8);
                }
                asm volatile("cp.async.commit_group;" ::: "memory");
                asm volatile("cp.async.wait_group 1;" ::: "memory");
            } else {
                asm volatile("cp.async.wait_group 0;" ::: "memory");
            }
            __syncthreads();                                 // current buffer ready

            const uint32_t* As32 = reinterpret_cast<const uint32_t*>(smc + cur * 20480);
            const uint32_t* Bs32 = reinterpret_cast<const uint32_t*>(smc + 40960 + cur * 40960);
#pragma unroll
            for (int kk = 0; kk < 4; ++kk) {                 // 4 x k16
                const int ko = kk * 8 + 2 * t;               // uint32 offset in row
                uint32_t bh[4][2];
#pragma unroll
                for (int nt = 0; nt < 4; ++nt) {
                    const uint2 bv = *reinterpret_cast<const uint2*>(
                        Bs32 + (wn * 32 + nt * 8 + g) * 40 + ko);
                    bh[nt][0] = bv.x;
                    bh[nt][1] = bv.y;
                }
#pragma unroll
                for (int mt = 0; mt < 4; ++mt) {
                    const int ab = (wm * 64 + mt * 16 + g) * 40 + ko;
                    const uint2 a0 = *reinterpret_cast<const uint2*>(As32 + ab);
                    const uint2 a1 = *reinterpret_cast<const uint2*>(As32 + ab + 8 * 40);
                    uint32_t ah[4];
                    ah[0] = a0.x; ah[1] = a1.x; ah[2] = a0.y; ah[3] = a1.y;
#pragma unroll
                    for (int nt = 0; nt < 4; ++nt)
                        MMA_BF16(c[mt * 4 + nt], ah, bh[nt]);
                }
            }
            __syncthreads();                                 // reads done before overwrite
        }

        // epilogue: two 128-col halves through Ds
#pragma unroll
        for (int h = 0; h < 2; ++h) {
            if ((wn >> 2) == h) {
#pragma unroll
                for (int mt = 0; mt < 4; ++mt) {
#pragma unroll
                    for (int nt = 0; nt < 4; ++nt) {
                        const int r0 = wm * 64 + mt * 16 + g;
                        float* d0 = Ds + r0 * 132 + (wn & 3) * 32 + nt * 8 + 2 * t;
                        d0[0] = c[mt * 4 + nt][0];
                        d0[1] = c[mt * 4 + nt][1];
                        d0[8 * 132]     = c[mt * 4 + nt][2];
                        d0[8 * 132 + 1] = c[mt * 4 + nt][3];
                    }
                }
            }
            __syncthreads();
            if (tid < 256) {
                const float* drow = Ds + srow * 132 + sh * 64;
                const int colbase = jb + h * 128 + sh * 64;
                const int sqb = h * 128 + sh * 64;
                float* ld = listd + tid * 13;
                int*   li = listi + tid * 13;
#pragma unroll 4
                for (int s = 0; s < 64; s += 4) {
                    float4 g4 = *reinterpret_cast<const float4*>(drow + s);
#pragma unroll
                    for (int q = 0; q < 4; ++q) {
                        float v = fmaf(-2.0f, (&g4.x)[q], sqs[sqb + s + q]);
                        const int col = colbase + s + q;
                        if (v < thresh && col != rowg) {
                            int u = NC2 - 1;                 // smem insertion (rare)
                            while (u > 0 && ld[u - 1] > v) {
                                ld[u] = ld[u - 1]; li[u] = li[u - 1]; --u;
                            }
                            ld[u] = v; li[u] = col;
                            thresh = ld[NC2 - 1];
                        }
                    }
                }
            }
            __syncthreads();
        }
    }

    // dump candidate sets (rescore treats them as an unordered set)
    if (tid < 256) {
        int* dst = g_cand + (size_t)rowg * NCAND + sh * NC2;
#pragma unroll
        for (int q = 0; q < NC2; ++q) dst[q] = listi[tid * 13 + q];
    }
}

// ================= exact rescore: df64 d^2 on 24 candidates, rank top-10 =================
__global__ void rescore_kernel(const float* __restrict__ x) {
    const int warp = (blockIdx.x * blockDim.x + threadIdx.x) >> 5;
    const int lane = threadIdx.x & 31;
    if (warp >= NROWS) return;
    const int row = warp;
    const float2 sqr = g_sqd[row];
    const float* xr = x + (size_t)row * DIM;

    int myidx = 0;
    if (lane < NCAND) myidx = g_cand[(size_t)row * NCAND + lane];
    float myh = 0.f, myl = 0.f;

    for (int cc = 0; cc < NCAND; ++cc) {
        const int cidx = __shfl_sync(0xffffffffu, myidx, cc);
        const float* xc = x + (size_t)cidx * DIM;
        float hi = 0.f, lo = 0.f;
#pragma unroll
        for (int k = 0; k < 16; ++k) {
            float a = xr[lane + 32 * k];
            float b = xc[lane + 32 * k];
            float p = a * b;
            float e = fmaf(a, b, -p);
            float t2 = hi + p;
            float er = (fabsf(hi) >= fabsf(p)) ? ((hi - t2) + p) : ((p - t2) + hi);
            lo += er + e;
            hi = t2;
        }
#pragma unroll
        for (int o = 16; o > 0; o >>= 1) {
            float oh = __shfl_xor_sync(0xffffffffu, hi, o);
            float ol = __shfl_xor_sync(0xffffffffu, lo, o);
            float s = hi + oh;
            float e = (fabsf(hi) >= fabsf(oh)) ? ((hi - s) + oh) : ((oh - s) + hi);
            e += lo + ol;
            hi = s + e;
            lo = e - (hi - s);
        }
        const float2 sqc = g_sqd[cidx];
        float2 d2 = df_add(df_add(sqr, sqc), make_float2(-2.f * hi, -2.f * lo));
        if (lane == cc) { myh = d2.x; myl = d2.y; }
    }

    int rank = 0;
#pragma unroll
    for (int l = 0; l < NCAND; ++l) {
        float oh = __shfl_sync(0xffffffffu, myh, l);
        float ol = __shfl_sync(0xffffffffu, myl, l);
        int   oi = __shfl_sync(0xffffffffu, myidx, l);
        bool less = (oh < myh) || (oh == myh && (ol < myl || (ol == myl && oi < myidx)));
        rank += less;
    }
    if (lane < NCAND && rank < KNN)
        g_idx[(size_t)row * KNN + rank] = myidx;
}

// ================= gather-sum =================
__global__ void gather_kernel(float* __restrict__ out) {
    __shared__ int nb[KNN];
    const int row = blockIdx.x;
    if (threadIdx.x < KNN) nb[threadIdx.x] = g_idx[(size_t)row * KNN + threadIdx.x];
    __syncthreads();
    const int c = threadIdx.x * 4;
    float4 acc = make_float4(0.f, 0.f, 0.f, 0.f);
#pragma unroll
    for (int t = 0; t < KNN; ++t) {
        const float4 v = *reinterpret_cast<const float4*>(g_xw + (size_t)nb[t] * DIM + c);
        acc.x += v.x; acc.y += v.y; acc.z += v.z; acc.w += v.w;
    }
    *reinterpret_cast<float4*>(out + (size_t)row * DIM + c) = acc;
}

extern "C" void kernel_launch(void* const* d_in, const int* in_sizes, int n_in,
                              void* d_out, int out_size) {
    const float* x = (const float*)d_in[0];
    const float* A = (const float*)d_in[1];
    float* out = (float*)d_out;
    (void)in_sizes; (void)n_in; (void)out_size;

    cudaFuncSetAttribute(knn_kernel, cudaFuncAttributeMaxDynamicSharedMemorySize, 218112);

    tf_kernel<<<NROWS * DIM / 16 / 256, 256>>>(x);
    sq_kernel<<<NROWS / 8, 256>>>(x);
    xw_kernel<<<dim3(4, 128), 256>>>(x, A);
    knn_kernel<<<128, 512, 218112>>>();
    rescore_kernel<<<NROWS / 8, 256>>>(x);
    gather_kernel<<<NROWS, 128>>>(out);
}

// round 16
// speedup vs baseline: 1.2197x; 1.2197x over previous
#include <cuda_runtime.h>
#include <cuda_bf16.h>
#include <cstdint>

#define NROWS 16384
#define DIM   512
#define KNN   10
#define NC2   12          // candidates kept per scanner thread
#define NCAND 24          // candidates per row

// ---- device scratch (allocation-free rule) ----
__device__ float          g_xw[NROWS * DIM];   // x @ A
__device__ __nv_bfloat16  g_bfh[NROWS * DIM];  // x bf16 hi, k-permuted per 16-group
__device__ __nv_bfloat16  g_bfl[NROWS * DIM];  // x bf16 lo (residual), same layout
__device__ __nv_bfloat16  g_ath[DIM * DIM];    // A^T bf16 hi, [n][k] k-permuted
__device__ __nv_bfloat16  g_atl[DIM * DIM];    // A^T bf16 lo
__device__ float          g_sq[NROWS];         // fp32 row norms (recall scan)
__device__ float2         g_sqd[NROWS];        // df64 row norms (exact rescore)
__device__ int            g_cand[NROWS * NCAND];
__device__ int            g_idx[NROWS * KNN];

// ---- helpers ----
__device__ __forceinline__ float2 df_add(float2 a, float2 b) {
    float s = a.x + b.x;
    float e = (fabsf(a.x) >= fabsf(b.x)) ? ((a.x - s) + b.x) : ((b.x - s) + a.x);
    e += a.y + b.y;
    float hi = s + e;
    return make_float2(hi, e - (hi - s));
}
__device__ __forceinline__ uint32_t smem_u32(const void* p) {
    uint32_t a;
    asm("{ .reg .u64 t; cvta.to.shared.u64 t, %1; cvt.u32.u64 %0, t; }" : "=r"(a) : "l"(p));
    return a;
}
__device__ __forceinline__ void cpa16(uint32_t s, const void* g) {
    asm volatile("cp.async.cg.shared.global [%0], [%1], 16;" :: "r"(s), "l"(g));
}
__device__ __forceinline__ uint32_t pack_bf2(float f1, float f0) {  // lo=f0, hi=f1
    uint32_t o;
    asm("cvt.rn.bf16x2.f32 %0, %1, %2;" : "=r"(o) : "f"(f1), "f"(f0));
    return o;
}

// m16n8k16 bf16
#define MMA_BF16(c, a, b) \
    asm volatile("mma.sync.aligned.m16n8k16.row.col.f32.bf16.bf16.f32 " \
        "{%0,%1,%2,%3},{%4,%5,%6,%7},{%8,%9},{%0,%1,%2,%3};" \
        : "+f"((c)[0]), "+f"((c)[1]), "+f"((c)[2]), "+f"((c)[3]) \
        : "r"((a)[0]), "r"((a)[1]), "r"((a)[2]), "r"((a)[3]), \
          "r"((b)[0]), "r"((b)[1]))

// ================= prep: x -> bf16 hi/lo, k-permuted per 16-group =================
// Pair order per 16-group: (0,1),(8,9),(2,3),(10,11),(4,5),(12,13),(6,7),(14,15)
__global__ void tf_kernel(const float* __restrict__ x) {
    int gi = blockIdx.x * blockDim.x + threadIdx.x;    // 16-float group index
    const float4* src = reinterpret_cast<const float4*>(x) + (size_t)gi * 4;
    float k[16];
    float4 v0 = src[0], v1 = src[1], v2 = src[2], v3 = src[3];
    k[0]=v0.x; k[1]=v0.y; k[2]=v0.z; k[3]=v0.w;
    k[4]=v1.x; k[5]=v1.y; k[6]=v1.z; k[7]=v1.w;
    k[8]=v2.x; k[9]=v2.y; k[10]=v2.z; k[11]=v2.w;
    k[12]=v3.x; k[13]=v3.y; k[14]=v3.z; k[15]=v3.w;
    const int pi[8] = {0, 8, 2, 10, 4, 12, 6, 14};
    uint32_t oh[8], ol[8];
#pragma unroll
    for (int i = 0; i < 8; ++i) {
        float f0 = k[pi[i]], f1 = k[pi[i] + 1];
        float h0 = __bfloat162float(__float2bfloat16(f0));
        float h1 = __bfloat162float(__float2bfloat16(f1));
        oh[i] = pack_bf2(h1, h0);
        ol[i] = pack_bf2(f1 - h1, f0 - h0);
    }
    uint4* dh = reinterpret_cast<uint4*>(g_bfh) + (size_t)gi * 2;
    dh[0] = make_uint4(oh[0], oh[1], oh[2], oh[3]);
    dh[1] = make_uint4(oh[4], oh[5], oh[6], oh[7]);
    uint4* dl = reinterpret_cast<uint4*>(g_bfl) + (size_t)gi * 2;
    dl[0] = make_uint4(ol[0], ol[1], ol[2], ol[3]);
    dl[1] = make_uint4(ol[4], ol[5], ol[6], ol[7]);
}

// ================= prep: A -> A^T bf16 hi/lo, [n][k] k-permuted =================
__global__ void at_kernel(const float* __restrict__ A) {
    int idx = blockIdx.x * blockDim.x + threadIdx.x;   // 512 n x 32 groups
    int n = idx & 511, gi = idx >> 9;
    float k[16];
#pragma unroll
    for (int j = 0; j < 16; ++j) k[j] = A[(size_t)(gi * 16 + j) * DIM + n];
    const int pi[8] = {0, 8, 2, 10, 4, 12, 6, 14};
    uint32_t oh[8], ol[8];
#pragma unroll
    for (int i = 0; i < 8; ++i) {
        float f0 = k[pi[i]], f1 = k[pi[i] + 1];
        float h0 = __bfloat162float(__float2bfloat16(f0));
        float h1 = __bfloat162float(__float2bfloat16(f1));
        oh[i] = pack_bf2(h1, h0);
        ol[i] = pack_bf2(f1 - h1, f0 - h0);
    }
    uint4* dh = reinterpret_cast<uint4*>(g_ath + (size_t)n * DIM + gi * 16);
    dh[0] = make_uint4(oh[0], oh[1], oh[2], oh[3]);
    dh[1] = make_uint4(oh[4], oh[5], oh[6], oh[7]);
    uint4* dl = reinterpret_cast<uint4*>(g_atl + (size_t)n * DIM + gi * 16);
    dl[0] = make_uint4(ol[0], ol[1], ol[2], ol[3]);
    dl[1] = make_uint4(ol[4], ol[5], ol[6], ol[7]);
}

// ================= row norms (fp32 + df64) =================
__global__ void sq_kernel(const float* __restrict__ x) {
    int row  = (blockIdx.x * blockDim.x + threadIdx.x) >> 5;
    int lane = threadIdx.x & 31;
    if (row >= NROWS) return;
    const float* xr = x + (size_t)row * DIM;
    float hi = 0.f, lo = 0.f;
#pragma unroll
    for (int k = 0; k < 16; ++k) {
        float a = xr[lane + 32 * k];
        float p = a * a;
        float e = fmaf(a, a, -p);
        float t = hi + p;
        float er = (fabsf(hi) >= fabsf(p)) ? ((hi - t) + p) : ((p - t) + hi);
        lo += er + e;
        hi = t;
    }
#pragma unroll
    for (int o = 16; o > 0; o >>= 1) {
        float oh = __shfl_xor_sync(0xffffffffu, hi, o);
        float ol = __shfl_xor_sync(0xffffffffu, lo, o);
        float s = hi + oh;
        float e = (fabsf(hi) >= fabsf(oh)) ? ((hi - s) + oh) : ((oh - s) + hi);
        e += lo + ol;
        hi = s + e;
        lo = e - (hi - s);
    }
    if (lane == 0) { g_sqd[row] = make_float2(hi, lo); g_sq[row] = hi + lo; }
}

// ================= xW = x @ A via bf16x3 MMA =================
// Grid (2,128): bn = bx*256, bm = by*128. K-slab 32 (2 k16 groups), double-buffered.
// SMEM per stage 61440 B: Axh@0(10240) Axl@10240 Bh@20480(20480) Bl@40960. x2 = 122880.
// Row stride 80 B (20 u32): v2 frag loads conflict-free.
__global__ __launch_bounds__(256, 1) void xwb_kernel() {
    extern __shared__ char smc[];
    const uint32_t sbase = smem_u32(smc);
    const int tid  = threadIdx.x;
    const int lane = tid & 31, wid = tid >> 5;
    const int wn = wid & 3, wm = wid >> 2;       // warp grid 2(M) x 4(N); tile 64x64
    const int g = lane >> 2, t = lane & 3;
    const int bm = blockIdx.y * 128;
    const int bn = blockIdx.x * 256;

    float c[32][4];
#pragma unroll
    for (int i = 0; i < 32; ++i) { c[i][0] = 0.f; c[i][1] = 0.f; c[i][2] = 0.f; c[i][3] = 0.f; }

    // stage slab 0
    {
        const uint32_t st = sbase;
#pragma unroll
        for (int i = tid; i < 512; i += 256) {           // A-side: 128 rows x 4 chunks
            int r = i >> 2, cc = i & 3;
            cpa16(st + r * 80 + cc * 16,         g_bfh + (size_t)(bm + r) * DIM + cc * 8);
            cpa16(st + 10240 + r * 80 + cc * 16, g_bfl + (size_t)(bm + r) * DIM + cc * 8);
        }
#pragma unroll
        for (int i = tid; i < 1024; i += 256) {          // B-side: 256 rows x 4 chunks
            int r = i >> 2, cc = i & 3;
            cpa16(st + 20480 + r * 80 + cc * 16, g_ath + (size_t)(bn + r) * DIM + cc * 8);
            cpa16(st + 40960 + r * 80 + cc * 16, g_atl + (size_t)(bn + r) * DIM + cc * 8);
        }
        asm volatile("cp.async.commit_group;" ::: "memory");
    }

    for (int slab = 0; slab < 16; ++slab) {
        const int cur = slab & 1;
        if (slab < 15) {                                 // stage next, THEN wait
            const int nxt = (slab + 1) & 1;
            const int kb = (slab + 1) * 32;
            const uint32_t st = sbase + nxt * 61440;
#pragma unroll
            for (int i = tid; i < 512; i += 256) {
                int r = i >> 2, cc = i & 3;
                cpa16(st + r * 80 + cc * 16,         g_bfh + (size_t)(bm + r) * DIM + kb + cc * 8);
                cpa16(st + 10240 + r * 80 + cc * 16, g_bfl + (size_t)(bm + r) * DIM + kb + cc * 8);
            }
#pragma unroll
            for (int i = tid; i < 1024; i += 256) {
                int r = i >> 2, cc = i & 3;
                cpa16(st + 20480 + r * 80 + cc * 16, g_ath + (size_t)(bn + r) * DIM + kb + cc * 8);
                cpa16(st + 40960 + r * 80 + cc * 16, g_atl + (size_t)(bn + r) * DIM + kb + cc * 8);
            }
            asm volatile("cp.async.commit_group;" ::: "memory");
            asm volatile("cp.async.wait_group 1;" ::: "memory");
        } else {
            asm volatile("cp.async.wait_group 0;" ::: "memory");
        }
        __syncthreads();

        const uint32_t* Ah32 = reinterpret_cast<const uint32_t*>(smc + cur * 61440);
        const uint32_t* Al32 = reinterpret_cast<const uint32_t*>(smc + cur * 61440 + 10240);
        const uint32_t* Bh32 = reinterpret_cast<const uint32_t*>(smc + cur * 61440 + 20480);
        const uint32_t* Bl32 = reinterpret_cast<const uint32_t*>(smc + cur * 61440 + 40960);
#pragma unroll
        for (int kk = 0; kk < 2; ++kk) {                 // 2 x k16 per slab
            const int ko = kk * 8 + 2 * t;
            uint32_t bh[8][2], bl[8][2];
#pragma unroll
            for (int nt = 0; nt < 8; ++nt) {
                const int br = (wn * 64 + nt * 8 + g) * 20 + ko;
                const uint2 bvh = *reinterpret_cast<const uint2*>(Bh32 + br);
                const uint2 bvl = *reinterpret_cast<const uint2*>(Bl32 + br);
                bh[nt][0] = bvh.x; bh[nt][1] = bvh.y;
                bl[nt][0] = bvl.x; bl[nt][1] = bvl.y;
            }
#pragma unroll
            for (int mt = 0; mt < 4; ++mt) {
                const int ab = (wm * 64 + mt * 16 + g) * 20 + ko;
                const uint2 a0h = *reinterpret_cast<const uint2*>(Ah32 + ab);
                const uint2 a1h = *reinterpret_cast<const uint2*>(Ah32 + ab + 8 * 20);
                const uint2 a0l = *reinterpret_cast<const uint2*>(Al32 + ab);
                const uint2 a1l = *reinterpret_cast<const uint2*>(Al32 + ab + 8 * 20);
                uint32_t ah[4], al[4];
                ah[0] = a0h.x; ah[1] = a1h.x; ah[2] = a0h.y; ah[3] = a1h.y;
                al[0] = a0l.x; al[1] = a1l.x; al[2] = a0l.y; al[3] = a1l.y;
#pragma unroll
                for (int nt = 0; nt < 8; ++nt) {
                    MMA_BF16(c[mt * 8 + nt], ah, bh[nt]);   // xh*Ah
                    MMA_BF16(c[mt * 8 + nt], ah, bl[nt]);   // xh*Al
                    MMA_BF16(c[mt * 8 + nt], al, bh[nt]);   // xl*Ah
                }
            }
        }
        __syncthreads();
    }

    // store fragments directly to g_xw
#pragma unroll
    for (int mt = 0; mt < 4; ++mt) {
#pragma unroll
        for (int nt = 0; nt < 8; ++nt) {
            const int R = bm + wm * 64 + mt * 16 + g;
            const int C = bn + wn * 64 + nt * 8 + 2 * t;
            *reinterpret_cast<float2*>(g_xw + (size_t)R * DIM + C) =
                make_float2(c[mt * 8 + nt][0], c[mt * 8 + nt][1]);
            *reinterpret_cast<float2*>(g_xw + (size_t)(R + 8) * DIM + C) =
                make_float2(c[mt * 8 + nt][2], c[mt * 8 + nt][3]);
        }
    }
}

// ================= Gram recall: bf16 m16n8k16, R13 structure (proven 1747us) =================
// SMEM bytes: A stages 2x20480 @0; B stages 2x40960 @40960; sqs @122880;
//             Ds 128x132 f32 @123904. Total 191488 B. Row stride 160B.
__global__ __launch_bounds__(256, 1) void knn_kernel() {
    extern __shared__ char smc[];
    const uint32_t sbase = smem_u32(smc);
    float* sqs = reinterpret_cast<float*>(smc + 122880);
    float* Ds  = reinterpret_cast<float*>(smc + 123904);

    const int tid  = threadIdx.x;
    const int lane = tid & 31, wid = tid >> 5;
    const int wn = wid & 3, wm = wid >> 2;       // warp grid 2(M) x 4(N)
    const int g = lane >> 2, t = lane & 3;
    const int bm = blockIdx.x * 128;

    const int srow = tid >> 1, sh = tid & 1;     // 2 scanner threads / row
    const int rowg = bm + srow;

    const float FINF = __int_as_float(0x7f800000);
    float bestd[NC2];
    int   besti[NC2];
#pragma unroll
    for (int q = 0; q < NC2; ++q) { bestd[q] = FINF; besti[q] = 0; }

    for (int jt = 0; jt < 64; ++jt) {
        const int jb = jt * 256;
        __syncthreads();                 // prev j-tile scan done (sqs/Ds reuse)
        sqs[tid] = g_sq[jb + tid];

        float c[32][4];
#pragma unroll
        for (int i = 0; i < 32; ++i) { c[i][0] = 0.f; c[i][1] = 0.f; c[i][2] = 0.f; c[i][3] = 0.f; }

        // stage slab 0 (k 0..63) into buffer 0
        {
            const uint32_t sA = sbase, sB = sbase + 40960;
#pragma unroll
            for (int i = tid; i < 1024; i += 256) {          // A: 128 rows x 8 x 16B
                int r = i >> 3, cc = i & 7;
                cpa16(sA + r * 160 + cc * 16, g_bfh + (size_t)(bm + r) * DIM + cc * 8);
            }
#pragma unroll
            for (int i = tid; i < 2048; i += 256) {          // B: 256 rows x 8 x 16B
                int r = i >> 3, cc = i & 7;
                cpa16(sB + r * 160 + cc * 16, g_bfh + (size_t)(jb + r) * DIM + cc * 8);
            }
            asm volatile("cp.async.commit_group;" ::: "memory");
        }

        for (int slab = 0; slab < 8; ++slab) {               // 8 slabs of k=64
            const int cur = slab & 1;
            if (slab < 7) {                                  // stage next, THEN wait
                const int nxt = (slab + 1) & 1;
                const int kb = (slab + 1) * 64;
                const uint32_t sA = sbase + nxt * 20480;
                const uint32_t sB = sbase + 40960 + nxt * 40960;
#pragma unroll
                for (int i = tid; i < 1024; i += 256) {
                    int r = i >> 3, cc = i & 7;
                    cpa16(sA + r * 160 + cc * 16, g_bfh + (size_t)(bm + r) * DIM + kb + cc * 8);
                }
#pragma unroll
                for (int i = tid; i < 2048; i += 256) {
                    int r = i >> 3, cc = i & 7;
                    cpa16(sB + r * 160 + cc * 16, g_bfh + (size_t)(jb + r) * DIM + kb + cc * 8);
                }
                asm volatile("cp.async.commit_group;" ::: "memory");
                asm volatile("cp.async.wait_group 1;" ::: "memory");
            } else {
                asm volatile("cp.async.wait_group 0;" ::: "memory");
            }
            __syncthreads();                                 // current buffer ready

            const uint32_t* As32 = reinterpret_cast<const uint32_t*>(smc + cur * 20480);
            const uint32_t* Bs32 = reinterpret_cast<const uint32_t*>(smc + 40960 + cur * 40960);
#pragma unroll
            for (int kk = 0; kk < 4; ++kk) {                 // 4 x k16
                const int ko = kk * 8 + 2 * t;               // uint32 offset in row
                uint32_t bh[8][2];
#pragma unroll
                for (int nt = 0; nt < 8; ++nt) {
                    const uint2 bv = *reinterpret_cast<const uint2*>(
                        Bs32 + (wn * 64 + nt * 8 + g) * 40 + ko);
                    bh[nt][0] = bv.x;
                    bh[nt][1] = bv.y;
                }
#pragma unroll
                for (int mt = 0; mt < 4; ++mt) {
                    const int ab = (wm * 64 + mt * 16 + g) * 40 + ko;
                    const uint2 a0 = *reinterpret_cast<const uint2*>(As32 + ab);
                    const uint2 a1 = *reinterpret_cast<const uint2*>(As32 + ab + 8 * 40);
                    uint32_t ah[4];
                    ah[0] = a0.x; ah[1] = a1.x; ah[2] = a0.y; ah[3] = a1.y;
#pragma unroll
                    for (int nt = 0; nt < 8; ++nt)
                        MMA_BF16(c[mt * 8 + nt], ah, bh[nt]);
                }
            }
            __syncthreads();                                 // reads done before overwrite
        }

        // epilogue: two 128-col halves through Ds
#pragma unroll
        for (int h = 0; h < 2; ++h) {
            if ((wn >> 1) == h) {
#pragma unroll
                for (int mt = 0; mt < 4; ++mt) {
#pragma unroll
                    for (int nt = 0; nt < 8; ++nt) {
                        const int r0 = wm * 64 + mt * 16 + g;
                        float* d0 = Ds + r0 * 132 + (wn & 1) * 64 + nt * 8 + 2 * t;
                        d0[0] = c[mt * 8 + nt][0];
                        d0[1] = c[mt * 8 + nt][1];
                        d0[8 * 132]     = c[mt * 8 + nt][2];
                        d0[8 * 132 + 1] = c[mt * 8 + nt][3];
                    }
                }
            }
            __syncthreads();
            const float* drow = Ds + srow * 132 + sh * 64;
            const int colbase = jb + h * 128 + sh * 64;
            const int sqb = h * 128 + sh * 64;
#pragma unroll 4
            for (int s = 0; s < 64; s += 4) {
                float4 g4 = *reinterpret_cast<const float4*>(drow + s);
#pragma unroll
                for (int q = 0; q < 4; ++q) {
                    float v = fmaf(-2.0f, (&g4.x)[q], sqs[sqb + s + q]);
                    const int col = colbase + s + q;
                    if (v < bestd[NC2 - 1] && col != rowg) {
                        bestd[NC2 - 1] = v; besti[NC2 - 1] = col;
#pragma unroll
                        for (int u = NC2 - 1; u > 0; --u) {
                            if (bestd[u] < bestd[u - 1]) {
                                float td = bestd[u]; bestd[u] = bestd[u - 1]; bestd[u - 1] = td;
                                int ti = besti[u]; besti[u] = besti[u - 1]; besti[u - 1] = ti;
                            }
                        }
                    }
                }
            }
            __syncthreads();
        }
    }

    // dump candidate sets (rescore treats them as an unordered set)
    int* dst = g_cand + (size_t)rowg * NCAND + sh * NC2;
#pragma unroll
    for (int q = 0; q < NC2; ++q) dst[q] = besti[q];
}

// ================= exact rescore: df64 d^2 on 24 candidates, rank top-10 =================
__global__ void rescore_kernel(const float* __restrict__ x) {
    const int warp = (blockIdx.x * blockDim.x + threadIdx.x) >> 5;
    const int lane = threadIdx.x & 31;
    if (warp >= NROWS) return;
    const int row = warp;
    const float2 sqr = g_sqd[row];
    const float* xr = x + (size_t)row * DIM;

    int myidx = 0;
    if (lane < NCAND) myidx = g_cand[(size_t)row * NCAND + lane];
    float myh = 0.f, myl = 0.f;

    for (int cc = 0; cc < NCAND; ++cc) {
        const int cidx = __shfl_sync(0xffffffffu, myidx, cc);
        const float* xc = x + (size_t)cidx * DIM;
        float hi = 0.f, lo = 0.f;
#pragma unroll
        for (int k = 0; k < 16; ++k) {
            float a = xr[lane + 32 * k];
            float b = xc[lane + 32 * k];
            float p = a * b;
            float e = fmaf(a, b, -p);
            float t2 = hi + p;
            float er = (fabsf(hi) >= fabsf(p)) ? ((hi - t2) + p) : ((p - t2) + hi);
            lo += er + e;
            hi = t2;
        }
#pragma unroll
        for (int o = 16; o > 0; o >>= 1) {
            float oh = __shfl_xor_sync(0xffffffffu, hi, o);
            float ol = __shfl_xor_sync(0xffffffffu, lo, o);
            float s = hi + oh;
            float e = (fabsf(hi) >= fabsf(oh)) ? ((hi - s) + oh) : ((oh - s) + hi);
            e += lo + ol;
            hi = s + e;
            lo = e - (hi - s);
        }
        const float2 sqc = g_sqd[cidx];
        float2 d2 = df_add(df_add(sqr, sqc), make_float2(-2.f * hi, -2.f * lo));
        if (lane == cc) { myh = d2.x; myl = d2.y; }
    }

    int rank = 0;
#pragma unroll
    for (int l = 0; l < NCAND; ++l) {
        float oh = __shfl_sync(0xffffffffu, myh, l);
        float ol = __shfl_sync(0xffffffffu, myl, l);
        int   oi = __shfl_sync(0xffffffffu, myidx, l);
        bool less = (oh < myh) || (oh == myh && (ol < myl || (ol == myl && oi < myidx)));
        rank += less;
    }
    if (lane < NCAND && rank < KNN)
        g_idx[(size_t)row * KNN + rank] = myidx;
}

// ================= gather-sum =================
__global__ void gather_kernel(float* __restrict__ out) {
    __shared__ int nb[KNN];
    const int row = blockIdx.x;
    if (threadIdx.x < KNN) nb[threadIdx.x] = g_idx[(size_t)row * KNN + threadIdx.x];
    __syncthreads();
    const int c = threadIdx.x * 4;
    float4 acc = make_float4(0.f, 0.f, 0.f, 0.f);
#pragma unroll
    for (int t = 0; t < KNN; ++t) {
        const float4 v = *reinterpret_cast<const float4*>(g_xw + (size_t)nb[t] * DIM + c);
        acc.x += v.x; acc.y += v.y; acc.z += v.z; acc.w += v.w;
    }
    *reinterpret_cast<float4*>(out + (size_t)row * DIM + c) = acc;
}

extern "C" void kernel_launch(void* const* d_in, const int* in_sizes, int n_in,
                              void* d_out, int out_size) {
    const float* x = (const float*)d_in[0];
    const float* A = (const float*)d_in[1];
    float* out = (float*)d_out;
    (void)in_sizes; (void)n_in; (void)out_size;

    cudaFuncSetAttribute(knn_kernel, cudaFuncAttributeMaxDynamicSharedMemorySize, 191488);
    cudaFuncSetAttribute(xwb_kernel, cudaFuncAttributeMaxDynamicSharedMemorySize, 122880);

    tf_kernel<<<NROWS * DIM / 16 / 256, 256>>>(x);
    at_kernel<<<DIM * DIM / 16 / 256, 256>>>(A);
    sq_kernel<<<NROWS / 8, 256>>>(x);
    xwb_kernel<<<dim3(2, 128), 256, 122880>>>();
    knn_kernel<<<128, 256, 191488>>>();
    rescore_kernel<<<NROWS / 8, 256>>>(x);
    gather_kernel<<<NROWS, 128>>>(out);
}